// round 9
// baseline (speedup 1.0000x reference)
#include <cuda_runtime.h>
#include <cuda_fp16.h>
#include <math_constants.h>

// TropConv2D: x (8,32,32,32) f32, w (288,64) f32, bias (64) f32
// out (8,30,30,64) f32: max_k(p_k + w_kf) - min_k(p_k + w_kf) + bias_f
// K = 3*3*32, k = (ii*3 + jj)*32 + c (channel fastest)
//
// R8: block = (b, ho, 10-px chunk), 320 thr = 10 warps (warp = 2px x 32f).
// All hot loads from smem: w LDS.128 conflict-free, x LDS.128 *broadcast*
// (true 1-wavefront on LDS, unlike L1tex). 5 blocks/SM, 78% occ, one wave.
// x converted f32->fp16 inline during tile fill; only w has a prepass.

#define HO_ 30
#define WO_ 30

__device__ uint4 g_w4[2304];   // [step*64 + f], step = ij*4+q: channel-pairs 4q..4q+3

__device__ __forceinline__ unsigned packh2(float a, float b) {
    __half2 h = __floats2half2_rn(a, b);
    return *reinterpret_cast<unsigned*>(&h);
}
__device__ __forceinline__ __half2 as_h2(unsigned u) {
    return *reinterpret_cast<__half2*>(&u);
}

__global__ __launch_bounds__(256)
void trop_wprep(const float* __restrict__ w)
{
    const int t = blockIdx.x * 256 + threadIdx.x;   // 9*256 = 2304 exactly
    const int f  = t & 63;
    const int s  = t >> 6;          // step 0..35
    const int k0 = s * 8;           // (s>>2)*32 + (s&3)*8 == 8*s
    uint4 u;
    u.x = packh2(w[(k0 + 0) * 64 + f], w[(k0 + 1) * 64 + f]);
    u.y = packh2(w[(k0 + 2) * 64 + f], w[(k0 + 3) * 64 + f]);
    u.z = packh2(w[(k0 + 4) * 64 + f], w[(k0 + 5) * 64 + f]);
    u.w = packh2(w[(k0 + 6) * 64 + f], w[(k0 + 7) * 64 + f]);
    g_w4[t] = u;
}

__global__ __launch_bounds__(320, 5)
void trop_main(const float* __restrict__ x,
               const float* __restrict__ bias,
               float* __restrict__ out)
{
    __shared__ uint4    ws[2304];   // 36 KB: [step*64 + f]
    __shared__ unsigned xs[576];    // 2.25 KB: [(r*12 + col)*16 + chpair], fp16x2

    const int t     = threadIdx.x;
    const int chunk = blockIdx.x;   // 0..2
    const int ho    = blockIdx.y;   // 0..29
    const int b     = blockIdx.z;   // 0..7
    const int wo0   = chunk * 10;

    // ── fill w smem: 2304 uint4, coalesced copies ──
    #pragma unroll
    for (int i = 0; i < 7; i++) ws[t + i * 320] = g_w4[t + i * 320];
    if (t < 64) ws[2240 + t] = g_w4[2240 + t];

    // ── fill x tile: rows ho..ho+2, cols wo0..wo0+11, 32 ch; convert f32->h2 ──
    {
        const float2* xsrc = reinterpret_cast<const float2*>(
            x + (((b * 32) + ho) * 32 + wo0) * 32);
        #pragma unroll
        for (int i = t; i < 576; i += 320) {       // 2 iters (576 = 36*16)
            const int rc = i >> 4;                 // 0..35 (r*12 + col)
            const int qp = i & 15;                 // channel pair
            const int r  = rc / 12;
            const int col = rc - r * 12;
            const float2 v = xsrc[(r * 32 + col) * 16 + qp];
            xs[i] = packh2(v.x, v.y);
        }
    }
    __syncthreads();

    const int wid   = t >> 5;
    const int lane  = t & 31;
    const int half  = wid & 1;      // filter half
    const int pairi = wid >> 1;     // pixel pair 0..4
    const int f     = half * 32 + lane;

    const uint4*    wsp = ws + half * 32 + lane;        // + step*64 (imm)
    const unsigned* xb0 = xs + (pairi * 2) * 16;        // px0 column base
    const unsigned* xb1 = xs + (pairi * 2 + 1) * 16;    // px1 column base

    const __half2 PINF = __float2half2_rn(CUDART_INF_F);
    const __half2 NINF = __float2half2_rn(-CUDART_INF_F);
    __half2 mxe0 = NINF, mxo0 = NINF, mne0 = PINF, mno0 = PINF;
    __half2 mxe1 = NINF, mxo1 = NINF, mne1 = PINF, mno1 = PINF;

    #pragma unroll
    for (int ij = 0; ij < 9; ij++) {
        const int ii = ij / 3;
        const int jj = ij - ii * 3;
        const int xofs = (ii * 12 + jj) * 16;      // compile-time per ij

        #pragma unroll
        for (int q = 0; q < 4; q++) {
            const uint4 wv  = wsp[(ij * 4 + q) * 64];
            const uint4 xv0 = *reinterpret_cast<const uint4*>(xb0 + xofs + q * 4);
            const uint4 xv1 = *reinterpret_cast<const uint4*>(xb1 + xofs + q * 4);

            const __half2 w0 = as_h2(wv.x), w1 = as_h2(wv.y),
                          w2 = as_h2(wv.z), w3 = as_h2(wv.w);
            {
                const __half2 p0 = as_h2(xv0.x), p1 = as_h2(xv0.y),
                              p2 = as_h2(xv0.z), p3 = as_h2(xv0.w);
                __half2 s0 = __hadd2(p0, w0);
                __half2 s1 = __hadd2(p1, w1);
                __half2 s2 = __hadd2(p2, w2);
                __half2 s3 = __hadd2(p3, w3);
                mxe0 = __hmax2(mxe0, s0); mne0 = __hmin2(mne0, s0);
                mxo0 = __hmax2(mxo0, s1); mno0 = __hmin2(mno0, s1);
                mxe0 = __hmax2(mxe0, s2); mne0 = __hmin2(mne0, s2);
                mxo0 = __hmax2(mxo0, s3); mno0 = __hmin2(mno0, s3);
            }
            {
                const __half2 p0 = as_h2(xv1.x), p1 = as_h2(xv1.y),
                              p2 = as_h2(xv1.z), p3 = as_h2(xv1.w);
                __half2 s0 = __hadd2(p0, w0);
                __half2 s1 = __hadd2(p1, w1);
                __half2 s2 = __hadd2(p2, w2);
                __half2 s3 = __hadd2(p3, w3);
                mxe1 = __hmax2(mxe1, s0); mne1 = __hmin2(mne1, s0);
                mxo1 = __hmax2(mxo1, s1); mno1 = __hmin2(mno1, s1);
                mxe1 = __hmax2(mxe1, s2); mne1 = __hmin2(mne1, s2);
                mxo1 = __hmax2(mxo1, s3); mno1 = __hmin2(mno1, s3);
            }
        }
    }

    const float bf = bias[f];
    const int pix0 = ((b * 30 + ho) * 30 + wo0 + pairi * 2);
    {
        const __half2 mx = __hmax2(mxe0, mxo0);
        const __half2 mn = __hmin2(mne0, mno0);
        const float m = fmaxf(__low2float(mx), __high2float(mx));
        const float n = fminf(__low2float(mn), __high2float(mn));
        out[pix0 * 64 + f] = m - n + bf;
    }
    {
        const __half2 mx = __hmax2(mxe1, mxo1);
        const __half2 mn = __hmin2(mne1, mno1);
        const float m = fmaxf(__low2float(mx), __high2float(mx));
        const float n = fminf(__low2float(mn), __high2float(mn));
        out[(pix0 + 1) * 64 + f] = m - n + bf;
    }
}

extern "C" void kernel_launch(void* const* d_in, const int* in_sizes, int n_in,
                              void* d_out, int out_size)
{
    const float* x    = (const float*)d_in[0];   // 262144
    const float* w    = (const float*)d_in[1];   // 18432
    const float* bias = (const float*)d_in[2];   // 64
    float* out = (float*)d_out;                  // 460800

    trop_wprep<<<9, 256>>>(w);
    // 720 blocks (3 chunks x 30 rows x 8 batches) x 320 thr = 7200 warps,
    // 5 blocks/SM (smem 39KB), single wave.
    dim3 grid(3, 30, 8);
    trop_main<<<grid, 320>>>(x, bias, out);
}

// round 11
// speedup vs baseline: 1.2814x; 1.2814x over previous
#include <cuda_runtime.h>
#include <cuda_fp16.h>
#include <math_constants.h>

// TropConv2D: x (8,32,32,32) f32, w (288,64) f32, bias (64) f32
// out (8,30,30,64) f32: max_k(p_k + w_kf) - min_k(p_k + w_kf) + bias_f
// K = 3*3*32, k = (ii*3 + jj)*32 + c (channel fastest)
//
// R9: exploit conv overlap. Warp = 3 consecutive pixels x 32 filters.
// Per (row ii, chunk q): load 5 shared x-columns (uint4, fp16x2) that serve
// all 3 taps x 3 pixels -> loads/compute = 8:108. w staged in smem.
// 4800 warps (32/SM), regs<=62 so ptxas can hoist next-step loads.

#define HO_ 30
#define WO_ 30

__device__ uint4 g_x8[32768];   // x as half, 8 consecutive channels per entry
__device__ uint4 g_w4[2304];    // [step*64 + f], step = ij*4+q (8 channels each)

__device__ __forceinline__ unsigned packh2(float a, float b) {
    __half2 h = __floats2half2_rn(a, b);
    return *reinterpret_cast<unsigned*>(&h);
}
__device__ __forceinline__ __half2 as_h2(unsigned u) {
    return *reinterpret_cast<__half2*>(&u);
}

__global__ __launch_bounds__(256)
void trop_prepass(const float4* __restrict__ x4, const float* __restrict__ w)
{
    const int t = blockIdx.x * 256 + threadIdx.x;   // covers 35072 = 137*256
    if (t < 32768) {
        const float4 a = x4[2 * t];
        const float4 b = x4[2 * t + 1];
        uint4 u;
        u.x = packh2(a.x, a.y);
        u.y = packh2(a.z, a.w);
        u.z = packh2(b.x, b.y);
        u.w = packh2(b.z, b.w);
        g_x8[t] = u;
    } else if (t < 35072) {
        const int wi = t - 32768;        // 0..2303
        const int f  = wi & 63;
        const int s  = wi >> 6;          // step 0..35
        const int k0 = s * 8;
        uint4 u;
        u.x = packh2(w[(k0 + 0) * 64 + f], w[(k0 + 1) * 64 + f]);
        u.y = packh2(w[(k0 + 2) * 64 + f], w[(k0 + 3) * 64 + f]);
        u.z = packh2(w[(k0 + 4) * 64 + f], w[(k0 + 5) * 64 + f]);
        u.w = packh2(w[(k0 + 6) * 64 + f], w[(k0 + 7) * 64 + f]);
        g_w4[wi] = u;
    }
}

__global__ __launch_bounds__(256, 4)
void trop_main(const float* __restrict__ bias, float* __restrict__ out)
{
    __shared__ uint4 ws[2304];   // 36 KB: [step*64 + f]

    const int t = threadIdx.x;
    #pragma unroll
    for (int i = 0; i < 9; i++) ws[t + i * 256] = g_w4[t + i * 256];
    __syncthreads();

    const int wg   = blockIdx.x * 8 + (t >> 5);   // 0..4799
    const int lane = t & 31;
    const int pg   = wg >> 1;                     // pixel triple 0..2399
    const int f    = (wg & 1) * 32 + lane;

    // pg -> (b, ho, 3-px chunk): 10 chunks per row
    const int R   = pg / 10;          // 0..239
    const int c3  = pg - R * 10;
    const int b   = R / 30;
    const int ho  = R - b * 30;
    const int wo0 = c3 * 3;

    const int xbase = ((b * 32 + ho) * 32 + wo0) * 4;   // uint4 index
    const uint4* __restrict__ wsp = ws + f;             // + step*64 (imm)

    const __half2 PINF = __float2half2_rn(CUDART_INF_F);
    const __half2 NINF = __float2half2_rn(-CUDART_INF_F);
    __half2 mxe[3], mxo[3], mne[3], mno[3];
    #pragma unroll
    for (int px = 0; px < 3; px++) {
        mxe[px] = NINF; mxo[px] = NINF;
        mne[px] = PINF; mno[px] = PINF;
    }

    #pragma unroll
    for (int ii = 0; ii < 3; ii++) {
        #pragma unroll
        for (int q = 0; q < 4; q++) {
            // 5 shared x columns: row ho+ii, cols wo0..wo0+4, channel chunk q
            uint4 xv[5];
            #pragma unroll
            for (int c = 0; c < 5; c++)
                xv[c] = __ldg(&g_x8[xbase + ii * 128 + c * 4 + q]);

            #pragma unroll
            for (int jj = 0; jj < 3; jj++) {
                const uint4 wv = wsp[((ii * 3 + jj) * 4 + q) * 64];
                const __half2 w0 = as_h2(wv.x), w1 = as_h2(wv.y),
                              w2 = as_h2(wv.z), w3 = as_h2(wv.w);
                #pragma unroll
                for (int px = 0; px < 3; px++) {
                    const uint4 xu = xv[jj + px];
                    const __half2 p0 = as_h2(xu.x), p1 = as_h2(xu.y),
                                  p2 = as_h2(xu.z), p3 = as_h2(xu.w);
                    __half2 s0 = __hadd2(p0, w0);
                    __half2 s1 = __hadd2(p1, w1);
                    __half2 s2 = __hadd2(p2, w2);
                    __half2 s3 = __hadd2(p3, w3);
                    mxe[px] = __hmax2(mxe[px], s0); mne[px] = __hmin2(mne[px], s0);
                    mxo[px] = __hmax2(mxo[px], s1); mno[px] = __hmin2(mno[px], s1);
                    mxe[px] = __hmax2(mxe[px], s2); mne[px] = __hmin2(mne[px], s2);
                    mxo[px] = __hmax2(mxo[px], s3); mno[px] = __hmin2(mno[px], s3);
                }
            }
        }
    }

    const float bf = bias[f];
    const int pix0 = (b * 30 + ho) * 30 + wo0;
    #pragma unroll
    for (int px = 0; px < 3; px++) {
        const __half2 mx = __hmax2(mxe[px], mxo[px]);
        const __half2 mn = __hmin2(mne[px], mno[px]);
        const float m = fmaxf(__low2float(mx), __high2float(mx));
        const float n = fminf(__low2float(mn), __high2float(mn));
        out[(pix0 + px) * 64 + f] = m - n + bf;
    }
}

extern "C" void kernel_launch(void* const* d_in, const int* in_sizes, int n_in,
                              void* d_out, int out_size)
{
    const float* x    = (const float*)d_in[0];   // 262144
    const float* w    = (const float*)d_in[1];   // 18432
    const float* bias = (const float*)d_in[2];   // 64
    float* out = (float*)d_out;                  // 460800

    trop_prepass<<<137, 256>>>((const float4*)x, w);
    // 4800 warps: 3 px x 32 f each; 600 blocks of 256 threads, 4 blocks/SM
    trop_main<<<600, 256>>>(bias, out);
}